// round 13
// baseline (speedup 1.0000x reference)
#include <cuda_runtime.h>

// Problem constants (fixed by the dataset)
#define NN 100000
#define EE 1600000
#define D  64
#define BN_EPS 1e-5f
#define NCH 98   // ceil(NN / 1024)
#define TM 64    // GEMM tile rows per block
#define XS 65    // padded row stride for X tile in shared

// ---------------- scratch (static device globals; no allocation) ----------------
// Self-cleaning invariant: at the START of every kernel_launch call,
//   g_deg == 0 (static zero-init on call 1; reset by k_apply thereafter)
// g_psum / g_bnsum are reset by block 0 of k_count (first kernel of the call)
// before their consumers (k_scan / k_agg / k_gemm / k_apply) run.
__device__ int   g_deg[NN];
__device__ float g_dis[NN];
__device__ int   g_rowptr[NN + 1];
__device__ int   g_fill[NN];               // seeded with rowptr; atomic bump = slot
__device__ int   g_psum[128];              // lookback aggregates (bit31 = ready)
__device__ int   g_col[EE];                // CSR column (src) only — no weights
__device__ __align__(16) float g_buf1[(size_t)NN * D];  // h' = dis[n] * (X@W)[n]
__device__ __align__(16) float g_buf2[(size_t)NN * D];  // aggregation outputs
__device__ float g_bnsum[4 * D];  // [sum1 | sq1 | sum2 | sq2]

// ---------------- kernels ----------------

// Edge histogram over dst (int4; EE % 4 == 0). deg counts EDGES only (no self
// loop; scan adds +1). Block 0 also resets psum/bnsum for this call.
__global__ void k_count(const int4* __restrict__ dst4) {
    if (blockIdx.x == 0) {
        int t = threadIdx.x;
        if (t < 4 * D) g_bnsum[t] = 0.0f;   // 256 floats
        if (t < 128)   g_psum[t]  = 0;
    }
    int stride = gridDim.x * blockDim.x;
    for (int e = blockIdx.x * blockDim.x + threadIdx.x; e < EE / 4; e += stride) {
        int4 d = __ldg(&dst4[e]);
        atomicAdd(&g_deg[d.x], 1);
        atomicAdd(&g_deg[d.y], 1);
        atomicAdd(&g_deg[d.z], 1);
        atomicAdd(&g_deg[d.w], 1);
    }
}

// Single-pass scan with decoupled lookback (98 blocks, all resident -> safe).
// deg holds edge counts (self loop NOT included); true degree = deg+1.
// Produces: g_dis = rsqrt(deg+1), g_rowptr = exclusive scan of deg,
// g_fill seeded with rowptr, g_rowptr[NN] = EE.
__global__ void k_scan() {
    __shared__ int s[1024];
    __shared__ int s_off[128];
    int t = threadIdx.x, b = blockIdx.x;
    int idx = b * 1024 + t;
    int d = 0;
    if (idx < NN) {
        d = g_deg[idx];                      // edges into idx
        g_dis[idx] = rsqrtf((float)(d + 1)); // +1 self loop
    }
    s[t] = d;
    __syncthreads();
    // Inclusive Hillis-Steele scan within the block.
    #pragma unroll
    for (int off = 1; off < 1024; off <<= 1) {
        int v = (t >= off) ? s[t - off] : 0;
        __syncthreads();
        s[t] += v;
        __syncthreads();
    }
    // Publish aggregate (payload inside the word; bit31 = ready flag).
    if (t == 0) atomicExch(&g_psum[b], s[1023] | 0x80000000);
    // Poll all predecessor aggregates in parallel (one per thread).
    int part = 0;
    if (t < b) {
        int v;
        do { v = *(volatile int*)&g_psum[t]; } while (!(v & 0x80000000));
        part = v & 0x7fffffff;
    }
    if (t < 128) s_off[t] = part;
    __syncthreads();
    #pragma unroll
    for (int o = 64; o > 0; o >>= 1) {
        if (t < o) s_off[t] += s_off[t + o];
        __syncthreads();
    }
    if (idx < NN) {
        int rp = s_off[0] + s[t] - d;  // exclusive
        g_rowptr[idx] = rp;
        g_fill[idx]   = rp;
    }
    if (b == NCH - 1 && t == 1023) g_rowptr[NN] = s_off[0] + s[1023];  // == EE
}

// Scatter edges into CSR buckets. Per edge: ONE returning atomic + ONE 4B store.
__global__ void k_scatter(const int4* __restrict__ src4, const int4* __restrict__ dst4) {
    int stride = gridDim.x * blockDim.x;
    for (int e = blockIdx.x * blockDim.x + threadIdx.x; e < EE / 4; e += stride) {
        int4 sv = __ldg(&src4[e]);
        int4 dv = __ldg(&dst4[e]);
        int o0 = atomicAdd(&g_fill[dv.x], 1);
        int o1 = atomicAdd(&g_fill[dv.y], 1);
        int o2 = atomicAdd(&g_fill[dv.z], 1);
        int o3 = atomicAdd(&g_fill[dv.w], 1);
        g_col[o0] = sv.x;
        g_col[o1] = sv.y;
        g_col[o2] = sv.z;
        g_col[o3] = sv.w;
    }
}

// Register-blocked GEMM: g_buf1 = dis[row] * (X @ W).
// mode 0: X = x_ext.  mode 1: X = g_buf2 with BatchNorm+ReLU fused into the
// shared-memory staging of X.
// Block = 256 threads (16x16), tile = 64 rows x 64 cols, 4x4 outputs/thread.
__global__ __launch_bounds__(256) void k_gemm(
        const float* __restrict__ X_ext,
        const float* __restrict__ W,
        const float* __restrict__ gamma,
        const float* __restrict__ beta,
        int mode) {
    __shared__ float Xs[TM * XS];
    __shared__ __align__(16) float Ws[D * D];
    __shared__ float s_sc[D], s_sh[D];
    int t = threadIdx.x;

    for (int i = t; i < D * D / 4; i += 256)
        ((float4*)Ws)[i] = ((const float4*)W)[i];
    if (mode == 1 && t < D) {
        float inv_n = 1.0f / (float)NN;
        float mu  = g_bnsum[t] * inv_n;
        float var = g_bnsum[D + t] * inv_n - mu * mu;
        float sc  = gamma[t] * rsqrtf(var + BN_EPS);
        s_sc[t] = sc;
        s_sh[t] = beta[t] - mu * sc;
    }
    __syncthreads();

    int row0 = blockIdx.x * TM;
    bool full = (row0 + TM <= NN);
    const float* X = (mode == 0) ? X_ext : g_buf2;

    // Stage X tile (64x64) into shared; BN+ReLU fused here in mode 1.
    #pragma unroll
    for (int i = t; i < TM * D / 4; i += 256) {
        int r  = i >> 4;            // 16 float4 per row
        int c4 = (i & 15) * 4;
        int gr = row0 + r;
        if (!full && gr >= NN) gr = NN - 1;  // clamp (store guarded later)
        float4 v = __ldg(&((const float4*)(X + (size_t)gr * D))[i & 15]);
        if (mode == 1) {
            v.x = fmaxf(fmaf(v.x, s_sc[c4],     s_sh[c4]),     0.0f);
            v.y = fmaxf(fmaf(v.y, s_sc[c4 + 1], s_sh[c4 + 1]), 0.0f);
            v.z = fmaxf(fmaf(v.z, s_sc[c4 + 2], s_sh[c4 + 2]), 0.0f);
            v.w = fmaxf(fmaf(v.w, s_sc[c4 + 3], s_sh[c4 + 3]), 0.0f);
        }
        float* xp = Xs + r * XS + c4;
        xp[0] = v.x; xp[1] = v.y; xp[2] = v.z; xp[3] = v.w;
    }
    __syncthreads();

    int tx = t & 15, ty = t >> 4;
    int r0 = ty * 4, c0 = tx * 4;
    float acc[4][4] = {};
    #pragma unroll 8
    for (int k = 0; k < D; k++) {
        float a0 = Xs[(r0 + 0) * XS + k];
        float a1 = Xs[(r0 + 1) * XS + k];
        float a2 = Xs[(r0 + 2) * XS + k];
        float a3 = Xs[(r0 + 3) * XS + k];
        float4 wv = *(const float4*)(Ws + k * D + c0);
        acc[0][0] = fmaf(a0, wv.x, acc[0][0]);
        acc[0][1] = fmaf(a0, wv.y, acc[0][1]);
        acc[0][2] = fmaf(a0, wv.z, acc[0][2]);
        acc[0][3] = fmaf(a0, wv.w, acc[0][3]);
        acc[1][0] = fmaf(a1, wv.x, acc[1][0]);
        acc[1][1] = fmaf(a1, wv.y, acc[1][1]);
        acc[1][2] = fmaf(a1, wv.z, acc[1][2]);
        acc[1][3] = fmaf(a1, wv.w, acc[1][3]);
        acc[2][0] = fmaf(a2, wv.x, acc[2][0]);
        acc[2][1] = fmaf(a2, wv.y, acc[2][1]);
        acc[2][2] = fmaf(a2, wv.z, acc[2][2]);
        acc[2][3] = fmaf(a2, wv.w, acc[2][3]);
        acc[3][0] = fmaf(a3, wv.x, acc[3][0]);
        acc[3][1] = fmaf(a3, wv.y, acc[3][1]);
        acc[3][2] = fmaf(a3, wv.z, acc[3][2]);
        acc[3][3] = fmaf(a3, wv.w, acc[3][3]);
    }

    // Store 4x4 with dis[row] scaling folded in.
    #pragma unroll
    for (int i = 0; i < 4; i++) {
        int gr = row0 + r0 + i;
        if (gr < NN) {
            float dr = g_dis[gr];
            float4 o = make_float4(acc[i][0] * dr, acc[i][1] * dr,
                                   acc[i][2] * dr, acc[i][3] * dr);
            *(float4*)(g_buf1 + (size_t)gr * D + c0) = o;
        }
    }
}

// Pull aggregation: HALF-WARP per node (float4 lanes), 2-edge dual-accumulator
// inner loop -> ~8 independent gathers in flight per half-warp.
//   g_buf2[n] = bias + dis[n] * ( h'[n] + sum_e h'[col[e]] )
// FUSED BN stats: per-feature sum/sumsq, halves combined via shfl, block
// reduce, one atomic per feature. Requires blockDim == 256, NN even.
__global__ void k_agg(const float* __restrict__ bias, int off) {
    __shared__ float ssum[8 * D], ssq[8 * D];
    int t = threadIdx.x;
    int warp = t >> 5, lane = t & 31;
    int half = lane >> 4, hl = lane & 15;     // half-warp id, lane within half
    int gwarp  = blockIdx.x * 8 + warp;
    int nwarps = gridDim.x * 8;
    const float4* __restrict__ H4 = (const float4*)g_buf1;
    float4 b = ((const float4*)bias)[hl];
    float4 ts = make_float4(0.f, 0.f, 0.f, 0.f);
    float4 tq = make_float4(0.f, 0.f, 0.f, 0.f);
    for (int pair = gwarp; pair < NN / 2; pair += nwarps) {
        int n = 2 * pair + half;
        float dn = g_dis[n];
        float4 acc  = __ldg(&H4[(size_t)n * 16 + hl]);  // self term h'[n]
        float4 acc2 = make_float4(0.f, 0.f, 0.f, 0.f);
        int s0 = g_rowptr[n], e0 = g_rowptr[n + 1];
        int i = s0;
        // Dual-accumulator 2-edge unroll: both col loads then both gathers
        // issue before any accumulate -> deeper MLP, split FADD chains.
        #pragma unroll 2
        for (; i + 2 <= e0; i += 2) {
            int c0 = __ldg(&g_col[i]);
            int c1 = __ldg(&g_col[i + 1]);
            float4 v0 = __ldg(&H4[(size_t)c0 * 16 + hl]);
            float4 v1 = __ldg(&H4[(size_t)c1 * 16 + hl]);
            acc.x  += v0.x; acc.y  += v0.y; acc.z  += v0.z; acc.w  += v0.w;
            acc2.x += v1.x; acc2.y += v1.y; acc2.z += v1.z; acc2.w += v1.w;
        }
        if (i < e0) {
            int c0 = __ldg(&g_col[i]);
            float4 v0 = __ldg(&H4[(size_t)c0 * 16 + hl]);
            acc.x += v0.x; acc.y += v0.y; acc.z += v0.z; acc.w += v0.w;
        }
        acc.x += acc2.x; acc.y += acc2.y; acc.z += acc2.z; acc.w += acc2.w;
        float4 o;
        o.x = fmaf(dn, acc.x, b.x);
        o.y = fmaf(dn, acc.y, b.y);
        o.z = fmaf(dn, acc.z, b.z);
        o.w = fmaf(dn, acc.w, b.w);
        ((float4*)g_buf2)[(size_t)n * 16 + hl] = o;
        ts.x += o.x; ts.y += o.y; ts.z += o.z; ts.w += o.w;
        tq.x = fmaf(o.x, o.x, tq.x);
        tq.y = fmaf(o.y, o.y, tq.y);
        tq.z = fmaf(o.z, o.z, tq.z);
        tq.w = fmaf(o.w, o.w, tq.w);
    }
    __syncwarp();
    // Combine the two halves (same features) with shuffles.
    ts.x += __shfl_down_sync(0xffffffffu, ts.x, 16);
    ts.y += __shfl_down_sync(0xffffffffu, ts.y, 16);
    ts.z += __shfl_down_sync(0xffffffffu, ts.z, 16);
    ts.w += __shfl_down_sync(0xffffffffu, ts.w, 16);
    tq.x += __shfl_down_sync(0xffffffffu, tq.x, 16);
    tq.y += __shfl_down_sync(0xffffffffu, tq.y, 16);
    tq.z += __shfl_down_sync(0xffffffffu, tq.z, 16);
    tq.w += __shfl_down_sync(0xffffffffu, tq.w, 16);
    if (half == 0) {
        ((float4*)(ssum + warp * D))[hl] = ts;
        ((float4*)(ssq  + warp * D))[hl] = tq;
    }
    __syncthreads();
    if (t < D) {
        float s = 0.0f, q = 0.0f;
        #pragma unroll
        for (int w = 0; w < 8; w++) {
            s += ssum[w * D + t];
            q += ssq [w * D + t];
        }
        atomicAdd(&g_bnsum[off + t],     s);
        atomicAdd(&g_bnsum[off + D + t], q);
    }
}

// Final BN+ReLU from g_buf2 (stats g_bnsum[128..255]) -> d_out. float4.
// Also resets g_deg for the NEXT call (no reader of g_deg in this kernel).
__global__ void k_apply(float4* __restrict__ out,
                        const float* __restrict__ gamma,
                        const float* __restrict__ beta) {
    __shared__ float s_sc[D], s_sh[D];
    int t = threadIdx.x;
    if (t < D) {
        float inv_n = 1.0f / (float)NN;
        float mu  = g_bnsum[128 + t] * inv_n;
        float var = g_bnsum[192 + t] * inv_n - mu * mu;
        float sc  = gamma[t] * rsqrtf(var + BN_EPS);
        s_sc[t] = sc;
        s_sh[t] = beta[t] - mu * sc;
    }
    __syncthreads();
    const float4* __restrict__ in = (const float4*)g_buf2;
    size_t total  = (size_t)NN * (D / 4);
    size_t stride = (size_t)gridDim.x * blockDim.x;
    for (size_t i = (size_t)blockIdx.x * blockDim.x + t; i < total; i += stride) {
        int f = ((int)i & 15) * 4;
        float4 v = in[i];
        v.x = fmaxf(fmaf(v.x, s_sc[f],     s_sh[f]),     0.0f);
        v.y = fmaxf(fmaf(v.y, s_sc[f + 1], s_sh[f + 1]), 0.0f);
        v.z = fmaxf(fmaf(v.z, s_sc[f + 2], s_sh[f + 2]), 0.0f);
        v.w = fmaxf(fmaf(v.w, s_sc[f + 3], s_sh[f + 3]), 0.0f);
        out[i] = v;
    }
    // Self-clean for next call.
    for (int i = blockIdx.x * blockDim.x + t; i < NN; i += (int)stride)
        g_deg[i] = 0;
}

// ---------------- launch ----------------
extern "C" void kernel_launch(void* const* d_in, const int* in_sizes, int n_in,
                              void* d_out, int out_size) {
    const float* x   = (const float*)d_in[0];
    const int*   ei  = (const int*)  d_in[1];
    const float* W1  = (const float*)d_in[2];
    const float* b1  = (const float*)d_in[3];
    const float* ga1 = (const float*)d_in[4];
    const float* be1 = (const float*)d_in[5];
    const float* W2  = (const float*)d_in[6];
    const float* b2  = (const float*)d_in[7];
    const float* ga2 = (const float*)d_in[8];
    const float* be2 = (const float*)d_in[9];
    float* out = (float*)d_out;

    const int4* src4 = (const int4*)ei;         // edge_index[0]
    const int4* dst4 = (const int4*)(ei + EE);  // edge_index[1]

    const int TB = 256;
    const int GEMM_BLKS = (NN + TM - 1) / TM;   // 1563
    const int WORK_BLKS = 1480;                 // grid-stride for agg

    // CSR build (k_count also resets psum/bnsum for this call)
    k_count  <<<2048, TB>>>(dst4);
    k_scan   <<<NCH, 1024>>>();
    k_scatter<<<2048, TB>>>(src4, dst4);

    // Layer 1
    k_gemm <<<GEMM_BLKS, TB>>>(x, W1, nullptr, nullptr, 0);   // buf1 = dis*(x@W1)
    k_agg  <<<WORK_BLKS, TB>>>(b1, 0);                        // buf2 = agg+b1, stats->[0:128)

    // Layer 2 (BN1+ReLU fused into GEMM staging)
    k_gemm <<<GEMM_BLKS, TB>>>(nullptr, W2, ga1, be1, 1);     // buf1 = dis*(relu(bn(buf2))@W2)
    k_agg  <<<WORK_BLKS, TB>>>(b2, 128);                      // buf2 = agg+b2, stats->[128:256)

    // Output (+ self-clean g_deg for next call)
    k_apply<<<2048, TB>>>((float4*)out, ga2, be2);
}

// round 14
// speedup vs baseline: 1.1172x; 1.1172x over previous
#include <cuda_runtime.h>

// Problem constants (fixed by the dataset)
#define NN 100000
#define EE 1600000
#define D  64
#define BN_EPS 1e-5f
#define NCH 98   // ceil(NN / 1024)
#define TM 64    // GEMM tile rows per block
#define XS 65    // padded row stride for X tile in shared

// ---------------- scratch (static device globals; no allocation) ----------------
// Self-cleaning invariant: at the START of every kernel_launch call,
//   g_deg == 0 (static zero-init on call 1; reset by k_apply thereafter)
// g_psum / g_bnsum are reset by block 0 of k_count (first kernel of the call)
// before their consumers (k_scan / k_agg / k_gemm / k_apply) run.
__device__ int   g_deg[NN];
__device__ float g_dis[NN];
__device__ int   g_rowptr[NN + 1];
__device__ int   g_fill[NN];               // seeded with rowptr; atomic bump = slot
__device__ int   g_psum[128];              // lookback aggregates (bit31 = ready)
__device__ int   g_col[EE];                // CSR column (src) only — no weights
__device__ __align__(16) float g_buf1[(size_t)NN * D];  // h' = dis[n] * (X@W)[n]
__device__ __align__(16) float g_buf2[(size_t)NN * D];  // aggregation outputs
__device__ float g_bnsum[4 * D];  // [sum1 | sq1 | sum2 | sq2]

// ---------------- kernels ----------------

// Edge histogram over dst (int4; EE % 4 == 0). deg counts EDGES only (no self
// loop; scan adds +1). Block 0 also resets psum/bnsum for this call.
__global__ void k_count(const int4* __restrict__ dst4) {
    if (blockIdx.x == 0) {
        int t = threadIdx.x;
        if (t < 4 * D) g_bnsum[t] = 0.0f;   // 256 floats
        if (t < 128)   g_psum[t]  = 0;
    }
    int stride = gridDim.x * blockDim.x;
    for (int e = blockIdx.x * blockDim.x + threadIdx.x; e < EE / 4; e += stride) {
        int4 d = __ldg(&dst4[e]);
        atomicAdd(&g_deg[d.x], 1);
        atomicAdd(&g_deg[d.y], 1);
        atomicAdd(&g_deg[d.z], 1);
        atomicAdd(&g_deg[d.w], 1);
    }
}

// Single-pass scan with decoupled lookback (98 blocks, all resident -> safe).
// deg holds edge counts (self loop NOT included); true degree = deg+1.
// Produces: g_dis = rsqrt(deg+1), g_rowptr = exclusive scan of deg,
// g_fill seeded with rowptr, g_rowptr[NN] = EE.
__global__ void k_scan() {
    __shared__ int s[1024];
    __shared__ int s_off[128];
    int t = threadIdx.x, b = blockIdx.x;
    int idx = b * 1024 + t;
    int d = 0;
    if (idx < NN) {
        d = g_deg[idx];                      // edges into idx
        g_dis[idx] = rsqrtf((float)(d + 1)); // +1 self loop
    }
    s[t] = d;
    __syncthreads();
    // Inclusive Hillis-Steele scan within the block.
    #pragma unroll
    for (int off = 1; off < 1024; off <<= 1) {
        int v = (t >= off) ? s[t - off] : 0;
        __syncthreads();
        s[t] += v;
        __syncthreads();
    }
    // Publish aggregate (payload inside the word; bit31 = ready flag).
    if (t == 0) atomicExch(&g_psum[b], s[1023] | 0x80000000);
    // Poll all predecessor aggregates in parallel (one per thread).
    int part = 0;
    if (t < b) {
        int v;
        do { v = *(volatile int*)&g_psum[t]; } while (!(v & 0x80000000));
        part = v & 0x7fffffff;
    }
    if (t < 128) s_off[t] = part;
    __syncthreads();
    #pragma unroll
    for (int o = 64; o > 0; o >>= 1) {
        if (t < o) s_off[t] += s_off[t + o];
        __syncthreads();
    }
    if (idx < NN) {
        int rp = s_off[0] + s[t] - d;  // exclusive
        g_rowptr[idx] = rp;
        g_fill[idx]   = rp;
    }
    if (b == NCH - 1 && t == 1023) g_rowptr[NN] = s_off[0] + s[1023];  // == EE
}

// Scatter edges into CSR buckets. Per edge: ONE returning atomic + ONE 4B store.
__global__ void k_scatter(const int4* __restrict__ src4, const int4* __restrict__ dst4) {
    int stride = gridDim.x * blockDim.x;
    for (int e = blockIdx.x * blockDim.x + threadIdx.x; e < EE / 4; e += stride) {
        int4 sv = __ldg(&src4[e]);
        int4 dv = __ldg(&dst4[e]);
        int o0 = atomicAdd(&g_fill[dv.x], 1);
        int o1 = atomicAdd(&g_fill[dv.y], 1);
        int o2 = atomicAdd(&g_fill[dv.z], 1);
        int o3 = atomicAdd(&g_fill[dv.w], 1);
        g_col[o0] = sv.x;
        g_col[o1] = sv.y;
        g_col[o2] = sv.z;
        g_col[o3] = sv.w;
    }
}

// Register-blocked GEMM: g_buf1 = dis[row] * (X @ W).
// mode 0: X = x_ext.  mode 1: X = g_buf2 with BatchNorm+ReLU fused into the
// shared-memory staging of X.
// Block = 256 threads (16x16), tile = 64 rows x 64 cols, 4x4 outputs/thread.
__global__ __launch_bounds__(256) void k_gemm(
        const float* __restrict__ X_ext,
        const float* __restrict__ W,
        const float* __restrict__ gamma,
        const float* __restrict__ beta,
        int mode) {
    __shared__ float Xs[TM * XS];
    __shared__ __align__(16) float Ws[D * D];
    __shared__ float s_sc[D], s_sh[D];
    int t = threadIdx.x;

    for (int i = t; i < D * D / 4; i += 256)
        ((float4*)Ws)[i] = ((const float4*)W)[i];
    if (mode == 1 && t < D) {
        float inv_n = 1.0f / (float)NN;
        float mu  = g_bnsum[t] * inv_n;
        float var = g_bnsum[D + t] * inv_n - mu * mu;
        float sc  = gamma[t] * rsqrtf(var + BN_EPS);
        s_sc[t] = sc;
        s_sh[t] = beta[t] - mu * sc;
    }
    __syncthreads();

    int row0 = blockIdx.x * TM;
    bool full = (row0 + TM <= NN);
    const float* X = (mode == 0) ? X_ext : g_buf2;

    // Stage X tile (64x64) into shared; BN+ReLU fused here in mode 1.
    #pragma unroll
    for (int i = t; i < TM * D / 4; i += 256) {
        int r  = i >> 4;            // 16 float4 per row
        int c4 = (i & 15) * 4;
        int gr = row0 + r;
        if (!full && gr >= NN) gr = NN - 1;  // clamp (store guarded later)
        float4 v = __ldg(&((const float4*)(X + (size_t)gr * D))[i & 15]);
        if (mode == 1) {
            v.x = fmaxf(fmaf(v.x, s_sc[c4],     s_sh[c4]),     0.0f);
            v.y = fmaxf(fmaf(v.y, s_sc[c4 + 1], s_sh[c4 + 1]), 0.0f);
            v.z = fmaxf(fmaf(v.z, s_sc[c4 + 2], s_sh[c4 + 2]), 0.0f);
            v.w = fmaxf(fmaf(v.w, s_sc[c4 + 3], s_sh[c4 + 3]), 0.0f);
        }
        float* xp = Xs + r * XS + c4;
        xp[0] = v.x; xp[1] = v.y; xp[2] = v.z; xp[3] = v.w;
    }
    __syncthreads();

    int tx = t & 15, ty = t >> 4;
    int r0 = ty * 4, c0 = tx * 4;
    float acc[4][4] = {};
    #pragma unroll 8
    for (int k = 0; k < D; k++) {
        float a0 = Xs[(r0 + 0) * XS + k];
        float a1 = Xs[(r0 + 1) * XS + k];
        float a2 = Xs[(r0 + 2) * XS + k];
        float a3 = Xs[(r0 + 3) * XS + k];
        float4 wv = *(const float4*)(Ws + k * D + c0);
        acc[0][0] = fmaf(a0, wv.x, acc[0][0]);
        acc[0][1] = fmaf(a0, wv.y, acc[0][1]);
        acc[0][2] = fmaf(a0, wv.z, acc[0][2]);
        acc[0][3] = fmaf(a0, wv.w, acc[0][3]);
        acc[1][0] = fmaf(a1, wv.x, acc[1][0]);
        acc[1][1] = fmaf(a1, wv.y, acc[1][1]);
        acc[1][2] = fmaf(a1, wv.z, acc[1][2]);
        acc[1][3] = fmaf(a1, wv.w, acc[1][3]);
        acc[2][0] = fmaf(a2, wv.x, acc[2][0]);
        acc[2][1] = fmaf(a2, wv.y, acc[2][1]);
        acc[2][2] = fmaf(a2, wv.z, acc[2][2]);
        acc[2][3] = fmaf(a2, wv.w, acc[2][3]);
        acc[3][0] = fmaf(a3, wv.x, acc[3][0]);
        acc[3][1] = fmaf(a3, wv.y, acc[3][1]);
        acc[3][2] = fmaf(a3, wv.z, acc[3][2]);
        acc[3][3] = fmaf(a3, wv.w, acc[3][3]);
    }

    // Store 4x4 with dis[row] scaling folded in.
    #pragma unroll
    for (int i = 0; i < 4; i++) {
        int gr = row0 + r0 + i;
        if (gr < NN) {
            float dr = g_dis[gr];
            float4 o = make_float4(acc[i][0] * dr, acc[i][1] * dr,
                                   acc[i][2] * dr, acc[i][3] * dr);
            *(float4*)(g_buf1 + (size_t)gr * D + c0) = o;
        }
    }
}

// Pull aggregation: HALF-WARP per node (float4 lanes) -> 2 independent edge
// streams per warp. R11 loop structure (compiler-pipelined unroll-4, single
// accumulator) with 32-bit hot-loop indexing (max index NN*16 < 2^31).
//   g_buf2[n] = bias + dis[n] * ( h'[n] + sum_e h'[col[e]] )
// FUSED BN stats: per-feature sum/sumsq, halves combined via shfl, block
// reduce, one atomic per feature. Requires blockDim == 256, NN even.
__global__ void k_agg(const float* __restrict__ bias, int off) {
    __shared__ float ssum[8 * D], ssq[8 * D];
    int t = threadIdx.x;
    int warp = t >> 5, lane = t & 31;
    int half = lane >> 4, hl = lane & 15;     // half-warp id, lane within half
    int gwarp  = blockIdx.x * 8 + warp;
    int nwarps = gridDim.x * 8;
    const float4* __restrict__ H4 = (const float4*)g_buf1;
    float4* __restrict__ O4 = (float4*)g_buf2;
    float4 b = ((const float4*)bias)[hl];
    float4 ts = make_float4(0.f, 0.f, 0.f, 0.f);
    float4 tq = make_float4(0.f, 0.f, 0.f, 0.f);
    for (int pair = gwarp; pair < NN / 2; pair += nwarps) {
        int n = 2 * pair + half;
        float dn = g_dis[n];
        unsigned nbase = ((unsigned)n << 4) + hl;
        float4 acc = __ldg(&H4[nbase]);                 // self term h'[n]
        int s0 = g_rowptr[n], e0 = g_rowptr[n + 1];
        #pragma unroll 4
        for (int i = s0; i < e0; i++) {
            int col = __ldg(&g_col[i]);                 // broadcast within half
            float4 v = __ldg(&H4[((unsigned)col << 4) + hl]);
            acc.x += v.x; acc.y += v.y; acc.z += v.z; acc.w += v.w;
        }
        float4 o;
        o.x = fmaf(dn, acc.x, b.x);
        o.y = fmaf(dn, acc.y, b.y);
        o.z = fmaf(dn, acc.z, b.z);
        o.w = fmaf(dn, acc.w, b.w);
        O4[nbase] = o;
        ts.x += o.x; ts.y += o.y; ts.z += o.z; ts.w += o.w;
        tq.x = fmaf(o.x, o.x, tq.x);
        tq.y = fmaf(o.y, o.y, tq.y);
        tq.z = fmaf(o.z, o.z, tq.z);
        tq.w = fmaf(o.w, o.w, tq.w);
    }
    __syncwarp();
    // Combine the two halves (same features) with shuffles.
    ts.x += __shfl_down_sync(0xffffffffu, ts.x, 16);
    ts.y += __shfl_down_sync(0xffffffffu, ts.y, 16);
    ts.z += __shfl_down_sync(0xffffffffu, ts.z, 16);
    ts.w += __shfl_down_sync(0xffffffffu, ts.w, 16);
    tq.x += __shfl_down_sync(0xffffffffu, tq.x, 16);
    tq.y += __shfl_down_sync(0xffffffffu, tq.y, 16);
    tq.z += __shfl_down_sync(0xffffffffu, tq.z, 16);
    tq.w += __shfl_down_sync(0xffffffffu, tq.w, 16);
    if (half == 0) {
        ((float4*)(ssum + warp * D))[hl] = ts;
        ((float4*)(ssq  + warp * D))[hl] = tq;
    }
    __syncthreads();
    if (t < D) {
        float s = 0.0f, q = 0.0f;
        #pragma unroll
        for (int w = 0; w < 8; w++) {
            s += ssum[w * D + t];
            q += ssq [w * D + t];
        }
        atomicAdd(&g_bnsum[off + t],     s);
        atomicAdd(&g_bnsum[off + D + t], q);
    }
}

// Final BN+ReLU from g_buf2 (stats g_bnsum[128..255]) -> d_out. float4.
// Also resets g_deg for the NEXT call (no reader of g_deg in this kernel).
__global__ void k_apply(float4* __restrict__ out,
                        const float* __restrict__ gamma,
                        const float* __restrict__ beta) {
    __shared__ float s_sc[D], s_sh[D];
    int t = threadIdx.x;
    if (t < D) {
        float inv_n = 1.0f / (float)NN;
        float mu  = g_bnsum[128 + t] * inv_n;
        float var = g_bnsum[192 + t] * inv_n - mu * mu;
        float sc  = gamma[t] * rsqrtf(var + BN_EPS);
        s_sc[t] = sc;
        s_sh[t] = beta[t] - mu * sc;
    }
    __syncthreads();
    const float4* __restrict__ in = (const float4*)g_buf2;
    size_t total  = (size_t)NN * (D / 4);
    size_t stride = (size_t)gridDim.x * blockDim.x;
    for (size_t i = (size_t)blockIdx.x * blockDim.x + t; i < total; i += stride) {
        int f = ((int)i & 15) * 4;
        float4 v = in[i];
        v.x = fmaxf(fmaf(v.x, s_sc[f],     s_sh[f]),     0.0f);
        v.y = fmaxf(fmaf(v.y, s_sc[f + 1], s_sh[f + 1]), 0.0f);
        v.z = fmaxf(fmaf(v.z, s_sc[f + 2], s_sh[f + 2]), 0.0f);
        v.w = fmaxf(fmaf(v.w, s_sc[f + 3], s_sh[f + 3]), 0.0f);
        out[i] = v;
    }
    // Self-clean for next call.
    for (int i = blockIdx.x * blockDim.x + t; i < NN; i += (int)stride)
        g_deg[i] = 0;
}

// ---------------- launch ----------------
extern "C" void kernel_launch(void* const* d_in, const int* in_sizes, int n_in,
                              void* d_out, int out_size) {
    const float* x   = (const float*)d_in[0];
    const int*   ei  = (const int*)  d_in[1];
    const float* W1  = (const float*)d_in[2];
    const float* b1  = (const float*)d_in[3];
    const float* ga1 = (const float*)d_in[4];
    const float* be1 = (const float*)d_in[5];
    const float* W2  = (const float*)d_in[6];
    const float* b2  = (const float*)d_in[7];
    const float* ga2 = (const float*)d_in[8];
    const float* be2 = (const float*)d_in[9];
    float* out = (float*)d_out;

    const int4* src4 = (const int4*)ei;         // edge_index[0]
    const int4* dst4 = (const int4*)(ei + EE);  // edge_index[1]

    const int TB = 256;
    const int GEMM_BLKS = (NN + TM - 1) / TM;   // 1563
    const int WORK_BLKS = 1480;                 // grid-stride for agg

    // CSR build (k_count also resets psum/bnsum for this call)
    k_count  <<<2048, TB>>>(dst4);
    k_scan   <<<NCH, 1024>>>();
    k_scatter<<<2048, TB>>>(src4, dst4);

    // Layer 1
    k_gemm <<<GEMM_BLKS, TB>>>(x, W1, nullptr, nullptr, 0);   // buf1 = dis*(x@W1)
    k_agg  <<<WORK_BLKS, TB>>>(b1, 0);                        // buf2 = agg+b1, stats->[0:128)

    // Layer 2 (BN1+ReLU fused into GEMM staging)
    k_gemm <<<GEMM_BLKS, TB>>>(nullptr, W2, ga1, be1, 1);     // buf1 = dis*(relu(bn(buf2))@W2)
    k_agg  <<<WORK_BLKS, TB>>>(b2, 128);                      // buf2 = agg+b2, stats->[128:256)

    // Output (+ self-clean g_deg for next call)
    k_apply<<<2048, TB>>>((float4*)out, ga2, be2);
}

// round 15
// speedup vs baseline: 1.1290x; 1.0105x over previous
#include <cuda_runtime.h>

// Problem constants (fixed by the dataset)
#define NN 100000
#define EE 1600000
#define D  64
#define BN_EPS 1e-5f
#define NCH 98   // ceil(NN / 1024)
#define TM 64    // GEMM tile rows per block
#define XS 68    // padded row stride for X tile (16B-aligned float4 reads, low conflict)

// ---------------- scratch (static device globals; no allocation) ----------------
// Self-cleaning invariant: at the START of every kernel_launch call,
//   g_deg == 0 (static zero-init on call 1; reset by k_apply thereafter)
// g_psum / g_bnsum are reset by block 0 of k_count (first kernel of the call)
// before their consumers (k_scan / k_agg / k_gemm / k_apply) run.
__device__ int   g_deg[NN];
__device__ float g_dis[NN];
__device__ int   g_rowptr[NN + 1];
__device__ int   g_fill[NN];               // seeded with rowptr; atomic bump = slot
__device__ int   g_psum[128];              // lookback aggregates (bit31 = ready)
__device__ int   g_col[EE];                // CSR column (src) only — no weights
__device__ __align__(16) float g_buf1[(size_t)NN * D];  // h' = dis[n] * (X@W)[n]
__device__ __align__(16) float g_buf2[(size_t)NN * D];  // aggregation outputs
__device__ float g_bnsum[4 * D];  // [sum1 | sq1 | sum2 | sq2]

// ---------------- kernels ----------------

// Edge histogram over dst (int4; EE % 4 == 0). deg counts EDGES only (no self
// loop; scan adds +1). Block 0 also resets psum/bnsum for this call.
__global__ void k_count(const int4* __restrict__ dst4) {
    if (blockIdx.x == 0) {
        int t = threadIdx.x;
        if (t < 4 * D) g_bnsum[t] = 0.0f;   // 256 floats
        if (t < 128)   g_psum[t]  = 0;
    }
    int stride = gridDim.x * blockDim.x;
    for (int e = blockIdx.x * blockDim.x + threadIdx.x; e < EE / 4; e += stride) {
        int4 d = __ldg(&dst4[e]);
        atomicAdd(&g_deg[d.x], 1);
        atomicAdd(&g_deg[d.y], 1);
        atomicAdd(&g_deg[d.z], 1);
        atomicAdd(&g_deg[d.w], 1);
    }
}

// Single-pass scan with decoupled lookback (98 blocks, all resident -> safe).
// deg holds edge counts (self loop NOT included); true degree = deg+1.
// Produces: g_dis = rsqrt(deg+1), g_rowptr = exclusive scan of deg,
// g_fill seeded with rowptr, g_rowptr[NN] = EE.
__global__ void k_scan() {
    __shared__ int s[1024];
    __shared__ int s_off[128];
    int t = threadIdx.x, b = blockIdx.x;
    int idx = b * 1024 + t;
    int d = 0;
    if (idx < NN) {
        d = g_deg[idx];                      // edges into idx
        g_dis[idx] = rsqrtf((float)(d + 1)); // +1 self loop
    }
    s[t] = d;
    __syncthreads();
    // Inclusive Hillis-Steele scan within the block.
    #pragma unroll
    for (int off = 1; off < 1024; off <<= 1) {
        int v = (t >= off) ? s[t - off] : 0;
        __syncthreads();
        s[t] += v;
        __syncthreads();
    }
    // Publish aggregate (payload inside the word; bit31 = ready flag).
    if (t == 0) atomicExch(&g_psum[b], s[1023] | 0x80000000);
    // Poll all predecessor aggregates in parallel (one per thread).
    int part = 0;
    if (t < b) {
        int v;
        do { v = *(volatile int*)&g_psum[t]; } while (!(v & 0x80000000));
        part = v & 0x7fffffff;
    }
    if (t < 128) s_off[t] = part;
    __syncthreads();
    #pragma unroll
    for (int o = 64; o > 0; o >>= 1) {
        if (t < o) s_off[t] += s_off[t + o];
        __syncthreads();
    }
    if (idx < NN) {
        int rp = s_off[0] + s[t] - d;  // exclusive
        g_rowptr[idx] = rp;
        g_fill[idx]   = rp;
    }
    if (b == NCH - 1 && t == 1023) g_rowptr[NN] = s_off[0] + s[1023];  // == EE
}

// Scatter edges into CSR buckets. Per edge: ONE returning atomic + ONE 4B store.
__global__ void k_scatter(const int4* __restrict__ src4, const int4* __restrict__ dst4) {
    int stride = gridDim.x * blockDim.x;
    for (int e = blockIdx.x * blockDim.x + threadIdx.x; e < EE / 4; e += stride) {
        int4 sv = __ldg(&src4[e]);
        int4 dv = __ldg(&dst4[e]);
        int o0 = atomicAdd(&g_fill[dv.x], 1);
        int o1 = atomicAdd(&g_fill[dv.y], 1);
        int o2 = atomicAdd(&g_fill[dv.z], 1);
        int o3 = atomicAdd(&g_fill[dv.w], 1);
        g_col[o0] = sv.x;
        g_col[o1] = sv.y;
        g_col[o2] = sv.z;
        g_col[o3] = sv.w;
    }
}

// Register-blocked GEMM: g_buf1 = dis[row] * (X @ W).
// mode 0: X = x_ext.  mode 1: X = g_buf2 with BatchNorm+ReLU fused into the
// shared-memory staging of X.
// Block = 256 threads (16x16), tile = 64x64, 4x4 outputs/thread.
// k-loop processes 4 k per iteration with float4 shared loads:
// 2x LDS.128 per k-step (vs 4x LDS.32 + 1x LDS.128) -> FMA-bound.
__global__ __launch_bounds__(256) void k_gemm(
        const float* __restrict__ X_ext,
        const float* __restrict__ W,
        const float* __restrict__ gamma,
        const float* __restrict__ beta,
        int mode) {
    __shared__ __align__(16) float Xs[TM * XS];
    __shared__ __align__(16) float Ws[D * D];
    __shared__ float s_sc[D], s_sh[D];
    int t = threadIdx.x;

    for (int i = t; i < D * D / 4; i += 256)
        ((float4*)Ws)[i] = ((const float4*)W)[i];
    if (mode == 1 && t < D) {
        float inv_n = 1.0f / (float)NN;
        float mu  = g_bnsum[t] * inv_n;
        float var = g_bnsum[D + t] * inv_n - mu * mu;
        float sc  = gamma[t] * rsqrtf(var + BN_EPS);
        s_sc[t] = sc;
        s_sh[t] = beta[t] - mu * sc;
    }
    __syncthreads();

    int row0 = blockIdx.x * TM;
    bool full = (row0 + TM <= NN);
    const float* X = (mode == 0) ? X_ext : g_buf2;

    // Stage X tile (64x64) into shared; BN+ReLU fused here in mode 1.
    #pragma unroll
    for (int i = t; i < TM * D / 4; i += 256) {
        int r  = i >> 4;            // 16 float4 per row
        int c4 = (i & 15) * 4;
        int gr = row0 + r;
        if (!full && gr >= NN) gr = NN - 1;  // clamp (store guarded later)
        float4 v = __ldg(&((const float4*)(X + (size_t)gr * D))[i & 15]);
        if (mode == 1) {
            v.x = fmaxf(fmaf(v.x, s_sc[c4],     s_sh[c4]),     0.0f);
            v.y = fmaxf(fmaf(v.y, s_sc[c4 + 1], s_sh[c4 + 1]), 0.0f);
            v.z = fmaxf(fmaf(v.z, s_sc[c4 + 2], s_sh[c4 + 2]), 0.0f);
            v.w = fmaxf(fmaf(v.w, s_sc[c4 + 3], s_sh[c4 + 3]), 0.0f);
        }
        *(float4*)(Xs + r * XS + c4) = v;    // XS=68 -> 16B aligned, no conflicts
    }
    __syncthreads();

    int tx = t & 15, ty = t >> 4;
    int r0 = ty * 4, c0 = tx * 4;
    float acc[4][4] = {};
    #pragma unroll 4
    for (int k4 = 0; k4 < D; k4 += 4) {
        // 4 X rows x 4 k-columns as float4 (ty-broadcast within warp)
        float4 xa0 = *(const float4*)(Xs + (r0 + 0) * XS + k4);
        float4 xa1 = *(const float4*)(Xs + (r0 + 1) * XS + k4);
        float4 xa2 = *(const float4*)(Xs + (r0 + 2) * XS + k4);
        float4 xa3 = *(const float4*)(Xs + (r0 + 3) * XS + k4);
        // 4 W rows (k4..k4+3), 4 cols each
        float4 w0 = *(const float4*)(Ws + (k4 + 0) * D + c0);
        float4 w1 = *(const float4*)(Ws + (k4 + 1) * D + c0);
        float4 w2 = *(const float4*)(Ws + (k4 + 2) * D + c0);
        float4 w3 = *(const float4*)(Ws + (k4 + 3) * D + c0);
        #define ROWSTEP(i, xa) \
            acc[i][0] = fmaf(xa.x, w0.x, acc[i][0]); \
            acc[i][1] = fmaf(xa.x, w0.y, acc[i][1]); \
            acc[i][2] = fmaf(xa.x, w0.z, acc[i][2]); \
            acc[i][3] = fmaf(xa.x, w0.w, acc[i][3]); \
            acc[i][0] = fmaf(xa.y, w1.x, acc[i][0]); \
            acc[i][1] = fmaf(xa.y, w1.y, acc[i][1]); \
            acc[i][2] = fmaf(xa.y, w1.z, acc[i][2]); \
            acc[i][3] = fmaf(xa.y, w1.w, acc[i][3]); \
            acc[i][0] = fmaf(xa.z, w2.x, acc[i][0]); \
            acc[i][1] = fmaf(xa.z, w2.y, acc[i][1]); \
            acc[i][2] = fmaf(xa.z, w2.z, acc[i][2]); \
            acc[i][3] = fmaf(xa.z, w2.w, acc[i][3]); \
            acc[i][0] = fmaf(xa.w, w3.x, acc[i][0]); \
            acc[i][1] = fmaf(xa.w, w3.y, acc[i][1]); \
            acc[i][2] = fmaf(xa.w, w3.z, acc[i][2]); \
            acc[i][3] = fmaf(xa.w, w3.w, acc[i][3]);
        ROWSTEP(0, xa0)
        ROWSTEP(1, xa1)
        ROWSTEP(2, xa2)
        ROWSTEP(3, xa3)
        #undef ROWSTEP
    }

    // Store 4x4 with dis[row] scaling folded in.
    #pragma unroll
    for (int i = 0; i < 4; i++) {
        int gr = row0 + r0 + i;
        if (gr < NN) {
            float dr = g_dis[gr];
            float4 o = make_float4(acc[i][0] * dr, acc[i][1] * dr,
                                   acc[i][2] * dr, acc[i][3] * dr);
            *(float4*)(g_buf1 + (size_t)gr * D + c0) = o;
        }
    }
}

// Pull aggregation: HALF-WARP per node (float4 lanes) -> 2 independent edge
// streams per warp. Compiler-pipelined unroll-4, single accumulator,
// 32-bit hot-loop indexing.
//   g_buf2[n] = bias + dis[n] * ( h'[n] + sum_e h'[col[e]] )
// FUSED BN stats: per-feature sum/sumsq, halves combined via shfl, block
// reduce, one atomic per feature. Requires blockDim == 256, NN even.
__global__ void k_agg(const float* __restrict__ bias, int off) {
    __shared__ float ssum[8 * D], ssq[8 * D];
    int t = threadIdx.x;
    int warp = t >> 5, lane = t & 31;
    int half = lane >> 4, hl = lane & 15;     // half-warp id, lane within half
    int gwarp  = blockIdx.x * 8 + warp;
    int nwarps = gridDim.x * 8;
    const float4* __restrict__ H4 = (const float4*)g_buf1;
    float4* __restrict__ O4 = (float4*)g_buf2;
    float4 b = ((const float4*)bias)[hl];
    float4 ts = make_float4(0.f, 0.f, 0.f, 0.f);
    float4 tq = make_float4(0.f, 0.f, 0.f, 0.f);
    for (int pair = gwarp; pair < NN / 2; pair += nwarps) {
        int n = 2 * pair + half;
        float dn = g_dis[n];
        unsigned nbase = ((unsigned)n << 4) + hl;
        float4 acc = __ldg(&H4[nbase]);                 // self term h'[n]
        int s0 = g_rowptr[n], e0 = g_rowptr[n + 1];
        #pragma unroll 4
        for (int i = s0; i < e0; i++) {
            int col = __ldg(&g_col[i]);                 // broadcast within half
            float4 v = __ldg(&H4[((unsigned)col << 4) + hl]);
            acc.x += v.x; acc.y += v.y; acc.z += v.z; acc.w += v.w;
        }
        float4 o;
        o.x = fmaf(dn, acc.x, b.x);
        o.y = fmaf(dn, acc.y, b.y);
        o.z = fmaf(dn, acc.z, b.z);
        o.w = fmaf(dn, acc.w, b.w);
        O4[nbase] = o;
        ts.x += o.x; ts.y += o.y; ts.z += o.z; ts.w += o.w;
        tq.x = fmaf(o.x, o.x, tq.x);
        tq.y = fmaf(o.y, o.y, tq.y);
        tq.z = fmaf(o.z, o.z, tq.z);
        tq.w = fmaf(o.w, o.w, tq.w);
    }
    __syncwarp();
    // Combine the two halves (same features) with shuffles.
    ts.x += __shfl_down_sync(0xffffffffu, ts.x, 16);
    ts.y += __shfl_down_sync(0xffffffffu, ts.y, 16);
    ts.z += __shfl_down_sync(0xffffffffu, ts.z, 16);
    ts.w += __shfl_down_sync(0xffffffffu, ts.w, 16);
    tq.x += __shfl_down_sync(0xffffffffu, tq.x, 16);
    tq.y += __shfl_down_sync(0xffffffffu, tq.y, 16);
    tq.z += __shfl_down_sync(0xffffffffu, tq.z, 16);
    tq.w += __shfl_down_sync(0xffffffffu, tq.w, 16);
    if (half == 0) {
        ((float4*)(ssum + warp * D))[hl] = ts;
        ((float4*)(ssq  + warp * D))[hl] = tq;
    }
    __syncthreads();
    if (t < D) {
        float s = 0.0f, q = 0.0f;
        #pragma unroll
        for (int w = 0; w < 8; w++) {
            s += ssum[w * D + t];
            q += ssq [w * D + t];
        }
        atomicAdd(&g_bnsum[off + t],     s);
        atomicAdd(&g_bnsum[off + D + t], q);
    }
}

// Final BN+ReLU from g_buf2 (stats g_bnsum[128..255]) -> d_out. float4.
// Also resets g_deg for the NEXT call (no reader of g_deg in this kernel).
__global__ void k_apply(float4* __restrict__ out,
                        const float* __restrict__ gamma,
                        const float* __restrict__ beta) {
    __shared__ float s_sc[D], s_sh[D];
    int t = threadIdx.x;
    if (t < D) {
        float inv_n = 1.0f / (float)NN;
        float mu  = g_bnsum[128 + t] * inv_n;
        float var = g_bnsum[192 + t] * inv_n - mu * mu;
        float sc  = gamma[t] * rsqrtf(var + BN_EPS);
        s_sc[t] = sc;
        s_sh[t] = beta[t] - mu * sc;
    }
    __syncthreads();
    const float4* __restrict__ in = (const float4*)g_buf2;
    size_t total  = (size_t)NN * (D / 4);
    size_t stride = (size_t)gridDim.x * blockDim.x;
    for (size_t i = (size_t)blockIdx.x * blockDim.x + t; i < total; i += stride) {
        int f = ((int)i & 15) * 4;
        float4 v = in[i];
        v.x = fmaxf(fmaf(v.x, s_sc[f],     s_sh[f]),     0.0f);
        v.y = fmaxf(fmaf(v.y, s_sc[f + 1], s_sh[f + 1]), 0.0f);
        v.z = fmaxf(fmaf(v.z, s_sc[f + 2], s_sh[f + 2]), 0.0f);
        v.w = fmaxf(fmaf(v.w, s_sc[f + 3], s_sh[f + 3]), 0.0f);
        out[i] = v;
    }
    // Self-clean for next call.
    for (int i = blockIdx.x * blockDim.x + t; i < NN; i += (int)stride)
        g_deg[i] = 0;
}

// ---------------- launch ----------------
extern "C" void kernel_launch(void* const* d_in, const int* in_sizes, int n_in,
                              void* d_out, int out_size) {
    const float* x   = (const float*)d_in[0];
    const int*   ei  = (const int*)  d_in[1];
    const float* W1  = (const float*)d_in[2];
    const float* b1  = (const float*)d_in[3];
    const float* ga1 = (const float*)d_in[4];
    const float* be1 = (const float*)d_in[5];
    const float* W2  = (const float*)d_in[6];
    const float* b2  = (const float*)d_in[7];
    const float* ga2 = (const float*)d_in[8];
    const float* be2 = (const float*)d_in[9];
    float* out = (float*)d_out;

    const int4* src4 = (const int4*)ei;         // edge_index[0]
    const int4* dst4 = (const int4*)(ei + EE);  // edge_index[1]

    const int TB = 256;
    const int GEMM_BLKS = (NN + TM - 1) / TM;   // 1563
    const int WORK_BLKS = 1480;                 // grid-stride for agg

    // CSR build (k_count also resets psum/bnsum for this call)
    k_count  <<<2048, TB>>>(dst4);
    k_scan   <<<NCH, 1024>>>();
    k_scatter<<<2048, TB>>>(src4, dst4);

    // Layer 1
    k_gemm <<<GEMM_BLKS, TB>>>(x, W1, nullptr, nullptr, 0);   // buf1 = dis*(x@W1)
    k_agg  <<<WORK_BLKS, TB>>>(b1, 0);                        // buf2 = agg+b1, stats->[0:128)

    // Layer 2 (BN1+ReLU fused into GEMM staging)
    k_gemm <<<GEMM_BLKS, TB>>>(nullptr, W2, ga1, be1, 1);     // buf1 = dis*(relu(bn(buf2))@W2)
    k_agg  <<<WORK_BLKS, TB>>>(b2, 128);                      // buf2 = agg+b2, stats->[128:256)

    // Output (+ self-clean g_deg for next call)
    k_apply<<<2048, TB>>>((float4*)out, ga2, be2);
}